// round 14
// baseline (speedup 1.0000x reference)
#include <cuda_runtime.h>
#include <cuda_fp16.h>

// 4-qubit depth-2 variational circuit, B=2^20 samples. Two kernels.
//
// Split: z_w = base_w + fp16 correction, where base_w = sign_w * prod_{q in
// mask_w} cos(x_q pi) is the EXACT weights->0 limit (CNOT conjugation maps
// Z_w to a multi-Z product; prep finds it numerically by rounding the 16
// pure-cos entries of T to integers), and the correction tensor T' = T - base
// is O(|weights|) ~ 0.02 -> fp16 Horner evaluation error ~1e-5 abs.
// main: 2 samples/thread, wire-pair half2 lanes, factored contraction
//   corr_w = sum_{i0} r0[i0] sum_{i1} r1[i1] sum_{i2} r2[i2] sum_{i3} r3[i3] T'.

__device__ uint2 g_T2h[81];   // .x = half2(T'_w0,T'_w1), .y = half2(T'_w2,T'_w3)
__device__ int   g_binfo[4];  // per wire: (mask bits3..0 = wires0..3) | code<<4
                              // code: 0 = none, 1 = +1, 2 = -1

__device__ __forceinline__ __half2 u2h(unsigned v) {
    return *reinterpret_cast<__half2*>(&v);
}
__device__ __forceinline__ unsigned h2u(__half2 h) {
    return *reinterpret_cast<unsigned*>(&h);
}

// ---------------- prep: shuffle-based gate evolution ----------------
__global__ void __launch_bounds__(256) qc_prep_kernel(const float* __restrict__ w) {
    __shared__ float bufR[16][16], bufI[16][16];  // [state s][column j]
    __shared__ float sA[4][16][16];
    __shared__ float2 sTrig[16];
    __shared__ float4 sT[81];
    const int tid = threadIdx.x;
    const unsigned FULL = 0xFFFFFFFFu;

    if (tid < 16) {
        float c, s;
        __sincosf(0.5f * w[tid], &s, &c);
        sTrig[tid] = make_float2(c, s);
    }
    // layout: column j = tid>>4, state s = tid&15  (pairs + perm stay in-warp)
    const int j = tid >> 4;
    const int s = tid & 15;
    const int lane = tid & 31;
    float ar = (s == j) ? 1.0f : 0.0f;
    float ai = 0.0f;
    __syncthreads();

#pragma unroll
    for (int d = 0; d < 2; ++d) {
        // composite CNOT ring permutation (validated bit map), via shfl
        int src = s;
        if (src & 1) src ^= 8;
        if (src & 2) src ^= 1;
        if (src & 4) src ^= 2;
        if (src & 8) src ^= 4;
        {
            float nar = __shfl_sync(FULL, ar, (lane & 16) | src);
            float nai = __shfl_sync(FULL, ai, (lane & 16) | src);
            ar = nar; ai = nai;
        }
#pragma unroll
        for (int q = 0; q < 4; ++q) {
            const int m = 8 >> q;
            float2 ty = sTrig[d * 8 + q * 2 + 0];
            float2 tz = sTrig[d * 8 + q * 2 + 1];
            float pr = __shfl_xor_sync(FULL, ar, m);
            float pi = __shfl_xor_sync(FULL, ai, m);
            float cy = ty.x, sy = ty.y, cp = tz.x, sp = tz.y;
            float nr, ni;
            if (s & m) { nr = cy * ar + sy * pr;  ni = cy * ai + sy * pi; }
            else       { nr = cy * ar - sy * pr;  ni = cy * ai - sy * pi; }
            if (s & m) { ar = nr * cp - ni * sp;  ai = ni * cp + nr * sp; }
            else       { ar = nr * cp + ni * sp;  ai = ni * cp - nr * sp; }
        }
    }
    bufR[s][j] = ar; bufI[s][j] = ai;
    __syncthreads();

    // stage 2: A_w[jj][jp]
#pragma unroll
    for (int e = tid; e < 1024; e += 256) {
        int wq = e >> 8;
        int jj = (e >> 4) & 15;
        int jp = e & 15;
        int mask = 8 >> wq;
        float acc = 0.f;
#pragma unroll
        for (int ss = 0; ss < 16; ++ss) {
            float v = bufR[ss][jj] * bufR[ss][jp] + bufI[ss][jj] * bufI[ss][jp];
            acc += (ss & mask) ? -v : v;
        }
        sA[wq][jj][jp] = acc;
    }
    __syncthreads();

    // stage 3a: fp32 tensor T into shared
    if (tid < 81) {
        int k = tid / 9, l = tid % 9;
        int i0 = k / 3, i1 = k % 3, i2 = l / 3, i3 = l % 3;
        int x0 = (i0 == 2), x1 = (i1 == 2), x2 = (i2 == 2), x3 = (i3 == 2);
        int n0 = (i0 == 1), n1 = (i1 == 1), n2 = (i2 == 1), n3 = (i3 == 1);
        float t4[4] = {0.f, 0.f, 0.f, 0.f};
#pragma unroll
        for (int c = 0; c < 16; ++c) {
            int o0 = (c >> 3) & 1, o1 = (c >> 2) & 1, o2 = (c >> 1) & 1, o3 = c & 1;
            int jj = (o0 << 3) | (o1 << 2) | (o2 << 1) | o3;
            int jp = ((o0 ^ x0) << 3) | ((o1 ^ x1) << 2) | ((o2 ^ x2) << 1) | (o3 ^ x3);
            int neg = (n0 & o0) ^ (n1 & o1) ^ (n2 & o2) ^ (n3 & o3);
            float sgn = neg ? -1.0f : 1.0f;
#pragma unroll
            for (int wq = 0; wq < 4; ++wq) t4[wq] += sgn * sA[wq][jj][jp];
        }
        const float inv16 = 1.0f / 16.0f;
        sT[tid] = make_float4(t4[0] * inv16, t4[1] * inv16,
                              t4[2] * inv16, t4[3] * inv16);
    }
    __syncthreads();

    // stage 3b: per wire, round pure-cos entries to integers; record dominant
    // (mask, sign) and subtract it in place. Pure-cos kl = all indices in {0,1}.
    if (tid < 4) {
        const int wq = tid;
        int info = 0;
#pragma unroll
        for (int c = 0; c < 16; ++c) {
            int b0 = (c >> 3) & 1, b1 = (c >> 2) & 1, b2 = (c >> 1) & 1, b3 = c & 1;
            int kl = 27 * b0 + 9 * b1 + 3 * b2 + b3;
            float* p = &((float*)&sT[kl])[wq];
            float v = *p;
            float r = rintf(v);
            if (r != 0.0f) {
                *p = v - r;
                info = c | ((r > 0.0f ? 1 : 2) << 4);
            }
        }
        g_binfo[wq] = info;
    }
    __syncthreads();

    // stage 3c: convert T' to half2 wire-pairs
    if (tid < 81) {
        float4 f = sT[tid];
        __half2 h01 = make_half2(__float2half_rn(f.x), __float2half_rn(f.y));
        __half2 h23 = make_half2(__float2half_rn(f.z), __float2half_rn(f.w));
        uint2 p; p.x = h2u(h01); p.y = h2u(h23);
        g_T2h[tid] = p;
    }
}

// base_w = sign * prod over masked wires of C[q]
__device__ __forceinline__ float base_eval(int info, const float* C) {
    int code = info >> 4;
    float b = (code == 1) ? 1.0f : ((code == 2) ? -1.0f : 0.0f);
    b *= (info & 8) ? C[0] : 1.0f;
    b *= (info & 4) ? C[1] : 1.0f;
    b *= (info & 2) ? C[2] : 1.0f;
    b *= (info & 1) ? C[3] : 1.0f;
    return b;
}

// ---------------- main: fp16 correction + fp32 product-of-cos base ----------------
__global__ void __launch_bounds__(256) qc_main_kernel(
    const float4* __restrict__ x, float4* __restrict__ out,
    const int* __restrict__ unused, int h /* B/2 */) {
    __shared__ uint2 Ts[81];
    __shared__ int sBI[4];
    int tid = threadIdx.x;
    if (tid < 81) Ts[tid] = g_T2h[tid];
    if (tid < 4) sBI[tid] = g_binfo[tid];
    __syncthreads();

    int t = blockIdx.x * 256 + tid;
    if (t >= h) return;

    const float PI_F = 3.14159265358979323846f;
    float4 xa = x[t];
    float4 xb = x[t + h];

    float Cf[2][4], Sf[2][4];
    __sincosf(xa.x * PI_F, &Sf[0][0], &Cf[0][0]);
    __sincosf(xa.y * PI_F, &Sf[0][1], &Cf[0][1]);
    __sincosf(xa.z * PI_F, &Sf[0][2], &Cf[0][2]);
    __sincosf(xa.w * PI_F, &Sf[0][3], &Cf[0][3]);
    __sincosf(xb.x * PI_F, &Sf[1][0], &Cf[1][0]);
    __sincosf(xb.y * PI_F, &Sf[1][1], &Cf[1][1]);
    __sincosf(xb.z * PI_F, &Sf[1][2], &Cf[1][2]);
    __sincosf(xb.w * PI_F, &Sf[1][3], &Cf[1][3]);

    __half2 CA[4], SA[4], CB[4], SB[4];
#pragma unroll
    for (int qb = 0; qb < 4; ++qb) {
        CA[qb] = __float2half2_rn(Cf[0][qb]);
        SA[qb] = __float2half2_rn(Sf[0][qb]);
        CB[qb] = __float2half2_rn(Cf[1][qb]);
        SB[qb] = __float2half2_rn(Sf[1][qb]);
    }

    __half2 zA0, zA1, zB0, zB1;

#pragma unroll
    for (int i0 = 0; i0 < 3; ++i0) {
        __half2 tA0, tA1, tB0, tB1;
#pragma unroll
        for (int i1 = 0; i1 < 3; ++i1) {
            const int base = (i0 * 3 + i1) * 9;
            __half2 uA0, uA1, uB0, uB1;
#pragma unroll
            for (int i2 = 0; i2 < 3; ++i2) {
                uint2 a = Ts[base + i2 * 3 + 0];
                uint2 b = Ts[base + i2 * 3 + 1];
                uint2 c = Ts[base + i2 * 3 + 2];
                __half2 Ta0 = u2h(a.x), Ta1 = u2h(a.y);
                __half2 Tb0 = u2h(b.x), Tb1 = u2h(b.y);
                __half2 Tc0 = u2h(c.x), Tc1 = u2h(c.y);
                __half2 vA0 = __hfma2(CA[3], Tb0, Ta0);
                __half2 vA1 = __hfma2(CA[3], Tb1, Ta1);
                __half2 vB0 = __hfma2(CB[3], Tb0, Ta0);
                __half2 vB1 = __hfma2(CB[3], Tb1, Ta1);
                vA0 = __hfma2(SA[3], Tc0, vA0);
                vA1 = __hfma2(SA[3], Tc1, vA1);
                vB0 = __hfma2(SB[3], Tc0, vB0);
                vB1 = __hfma2(SB[3], Tc1, vB1);
                if (i2 == 0) { uA0 = vA0; uA1 = vA1; uB0 = vB0; uB1 = vB1; }
                else if (i2 == 1) {
                    uA0 = __hfma2(CA[2], vA0, uA0);
                    uA1 = __hfma2(CA[2], vA1, uA1);
                    uB0 = __hfma2(CB[2], vB0, uB0);
                    uB1 = __hfma2(CB[2], vB1, uB1);
                } else {
                    uA0 = __hfma2(SA[2], vA0, uA0);
                    uA1 = __hfma2(SA[2], vA1, uA1);
                    uB0 = __hfma2(SB[2], vB0, uB0);
                    uB1 = __hfma2(SB[2], vB1, uB1);
                }
            }
            if (i1 == 0) { tA0 = uA0; tA1 = uA1; tB0 = uB0; tB1 = uB1; }
            else if (i1 == 1) {
                tA0 = __hfma2(CA[1], uA0, tA0);
                tA1 = __hfma2(CA[1], uA1, tA1);
                tB0 = __hfma2(CB[1], uB0, tB0);
                tB1 = __hfma2(CB[1], uB1, tB1);
            } else {
                tA0 = __hfma2(SA[1], uA0, tA0);
                tA1 = __hfma2(SA[1], uA1, tA1);
                tB0 = __hfma2(SB[1], uB0, tB0);
                tB1 = __hfma2(SB[1], uB1, tB1);
            }
        }
        if (i0 == 0) { zA0 = tA0; zA1 = tA1; zB0 = tB0; zB1 = tB1; }
        else if (i0 == 1) {
            zA0 = __hfma2(CA[0], tA0, zA0);
            zA1 = __hfma2(CA[0], tA1, zA1);
            zB0 = __hfma2(CB[0], tB0, zB0);
            zB1 = __hfma2(CB[0], tB1, zB1);
        } else {
            zA0 = __hfma2(SA[0], tA0, zA0);
            zA1 = __hfma2(SA[0], tA1, zA1);
            zB0 = __hfma2(SB[0], tB0, zB0);
            zB1 = __hfma2(SB[0], tB1, zB1);
        }
    }

    int b0 = sBI[0], b1 = sBI[1], b2 = sBI[2], b3 = sBI[3];
    out[t] = make_float4(base_eval(b0, Cf[0]) + __low2float(zA0),
                         base_eval(b1, Cf[0]) + __high2float(zA0),
                         base_eval(b2, Cf[0]) + __low2float(zA1),
                         base_eval(b3, Cf[0]) + __high2float(zA1));
    out[t + h] = make_float4(base_eval(b0, Cf[1]) + __low2float(zB0),
                             base_eval(b1, Cf[1]) + __high2float(zB0),
                             base_eval(b2, Cf[1]) + __low2float(zB1),
                             base_eval(b3, Cf[1]) + __high2float(zB1));
}

extern "C" void kernel_launch(void* const* d_in, const int* in_sizes, int n_in,
                              void* d_out, int out_size) {
    const float* x = (const float*)d_in[0];       // [B,4]
    const float* w = (const float*)d_in[1];       // [2,4,2]
    float* out = (float*)d_out;                   // [B,4]
    int B = in_sizes[0] / 4;
    int h = B / 2;

    qc_prep_kernel<<<1, 256>>>(w);
    int blocks = (h + 255) / 256;
    qc_main_kernel<<<blocks, 256>>>((const float4*)x, (float4*)out, nullptr, h);
}